// round 1
// baseline (speedup 1.0000x reference)
#include <cuda_runtime.h>
#include <cuda_bf16.h>
#include <math_constants.h>

// Problem constants
#define B_   2
#define S_   2048
#define D_   1024
#define H_   16
#define HD_  64
#define M_   (B_ * S_)      // 4096 rows for the projections

// ---------------------------------------------------------------------------
// Scratch buffers (allocation-free rule: __device__ globals)
// ---------------------------------------------------------------------------
__device__ float g_q[M_ * D_];
__device__ float g_k[M_ * D_];
__device__ float g_v[M_ * D_];
__device__ float g_att[M_ * D_];

// ---------------------------------------------------------------------------
// SGEMM:  C[M,N] = A[M,K] @ W[N,K]^T + bias[N]
// 128x128 block tile, BK=8, 256 threads, 8x8 micro-tile per thread.
// blockIdx.z selects among up to 3 (W, bias, C) triples (used for Q/K/V).
// ---------------------------------------------------------------------------
#define BM 128
#define BN 128
#define BK 8

__global__ __launch_bounds__(256)
void proj_gemm(const float* __restrict__ A,
               const float* __restrict__ W0, const float* __restrict__ W1, const float* __restrict__ W2,
               const float* __restrict__ b0, const float* __restrict__ b1, const float* __restrict__ b2,
               float* __restrict__ C0, float* __restrict__ C1, float* __restrict__ C2,
               int Mdim, int Ndim, int Kdim)
{
    __shared__ float As[BK][BM];
    __shared__ float Bs[BK][BN];

    const int z = blockIdx.z;
    const float* W    = (z == 0) ? W0 : (z == 1) ? W1 : W2;
    const float* bias = (z == 0) ? b0 : (z == 1) ? b1 : b2;
    float*       C    = (z == 0) ? C0 : (z == 1) ? C1 : C2;

    const int tid = threadIdx.x;
    const int tx  = tid & 15;        // 0..15  -> N direction
    const int ty  = tid >> 4;        // 0..15  -> M direction
    const int m0  = blockIdx.y * BM;
    const int n0  = blockIdx.x * BN;

    // loader coordinates: each thread loads one float4 of A and one of W
    const int lr = tid >> 1;         // 0..127 : row within tile
    const int lc = (tid & 1) * 4;    // 0 or 4 : col within 8-wide k-slab

    float acc[8][8];
#pragma unroll
    for (int i = 0; i < 8; i++)
#pragma unroll
        for (int j = 0; j < 8; j++) acc[i][j] = 0.f;

    const float* Arow = A + (size_t)(m0 + lr) * Kdim + lc;
    const float* Wrow = W + (size_t)(n0 + lr) * Kdim + lc;

    for (int k0 = 0; k0 < Kdim; k0 += BK) {
        float4 av = *(const float4*)(Arow + k0);
        float4 bv = *(const float4*)(Wrow + k0);
        __syncthreads();             // previous compute done before smem overwrite
        As[lc + 0][lr] = av.x; As[lc + 1][lr] = av.y;
        As[lc + 2][lr] = av.z; As[lc + 3][lr] = av.w;
        Bs[lc + 0][lr] = bv.x; Bs[lc + 1][lr] = bv.y;
        Bs[lc + 2][lr] = bv.z; Bs[lc + 3][lr] = bv.w;
        __syncthreads();

#pragma unroll
        for (int kk = 0; kk < BK; kk++) {
            float4 a0 = *(const float4*)&As[kk][ty * 8];
            float4 a1 = *(const float4*)&As[kk][ty * 8 + 4];
            float4 bb0 = *(const float4*)&Bs[kk][tx * 8];
            float4 bb1 = *(const float4*)&Bs[kk][tx * 8 + 4];
            float ar[8] = {a0.x, a0.y, a0.z, a0.w, a1.x, a1.y, a1.z, a1.w};
            float br[8] = {bb0.x, bb0.y, bb0.z, bb0.w, bb1.x, bb1.y, bb1.z, bb1.w};
#pragma unroll
            for (int i = 0; i < 8; i++)
#pragma unroll
                for (int j = 0; j < 8; j++)
                    acc[i][j] = fmaf(ar[i], br[j], acc[i][j]);
        }
    }

    // epilogue
#pragma unroll
    for (int i = 0; i < 8; i++) {
        const int row = m0 + ty * 8 + i;
        float* crow = C + (size_t)row * Ndim + n0 + tx * 8;
#pragma unroll
        for (int j4 = 0; j4 < 8; j4 += 4) {
            float4 o;
            o.x = acc[i][j4 + 0] + bias[n0 + tx * 8 + j4 + 0];
            o.y = acc[i][j4 + 1] + bias[n0 + tx * 8 + j4 + 1];
            o.z = acc[i][j4 + 2] + bias[n0 + tx * 8 + j4 + 2];
            o.w = acc[i][j4 + 3] + bias[n0 + tx * 8 + j4 + 3];
            *(float4*)(crow + j4) = o;
        }
    }
}

// ---------------------------------------------------------------------------
// Flash-attention (fp32, online softmax).
// Block: 256 threads (16x16), handles 64 query rows of one (b,h).
// Per thread: 4x4 tile of scores / output.  Row stats via half-warp shuffles.
// ---------------------------------------------------------------------------
#define BQ 64
#define BKV 64
#define SS_STRIDE 68   // padded stride for the P^T tile

__global__ __launch_bounds__(256)
void attn_kernel(const float* __restrict__ Q,
                 const float* __restrict__ K,
                 const float* __restrict__ V,
                 float* __restrict__ O)
{
    extern __shared__ float smem[];
    float* Qt  = smem;                 // [64][64]  Q transposed: Qt[d][r]
    float* Kst = Qt  + 64 * 64;        // [64][64]  K transposed: Kst[d][c]
    float* Vs  = Kst + 64 * 64;        // [64][64]  V natural:    Vs[k][c]
    float* Ss  = Vs  + 64 * 64;        // [64][SS_STRIDE] P transposed: Ss[k][r]

    const int tid = threadIdx.x;
    const int tx  = tid & 15;          // key-col group
    const int ty  = tid >> 4;          // query-row group
    const int b   = blockIdx.z;
    const int h   = blockIdx.y;
    const int q0  = blockIdx.x * BQ;

    const size_t headoff = (size_t)h * HD_;
    const float* Qbase = Q + ((size_t)(b * S_ + q0)) * D_ + headoff;

    // Load Q tile transposed, pre-scaled by 1/sqrt(Hd)
    for (int i = tid; i < 64 * 16; i += 256) {
        int r  = i >> 4;
        int c4 = (i & 15) * 4;
        float4 v = *(const float4*)(Qbase + (size_t)r * D_ + c4);
        Qt[(c4 + 0) * 64 + r] = v.x * 0.125f;
        Qt[(c4 + 1) * 64 + r] = v.y * 0.125f;
        Qt[(c4 + 2) * 64 + r] = v.z * 0.125f;
        Qt[(c4 + 3) * 64 + r] = v.w * 0.125f;
    }

    float acc[4][4];
    float m_i[4], l_i[4];
#pragma unroll
    for (int i = 0; i < 4; i++) {
        m_i[i] = -CUDART_INF_F; l_i[i] = 0.f;
#pragma unroll
        for (int j = 0; j < 4; j++) acc[i][j] = 0.f;
    }

    const int NT = S_ / BKV;
    for (int kt = 0; kt < NT; kt++) {
        const int k0 = kt * BKV;
        const float* Kbase = K + ((size_t)(b * S_ + k0)) * D_ + headoff;
        const float* Vbase = V + ((size_t)(b * S_ + k0)) * D_ + headoff;

        __syncthreads();   // previous PV / Q-load done before overwriting tiles
        for (int i = tid; i < 64 * 16; i += 256) {
            int r  = i >> 4;
            int c4 = (i & 15) * 4;
            float4 kv = *(const float4*)(Kbase + (size_t)r * D_ + c4);
            Kst[(c4 + 0) * 64 + r] = kv.x;
            Kst[(c4 + 1) * 64 + r] = kv.y;
            Kst[(c4 + 2) * 64 + r] = kv.z;
            Kst[(c4 + 3) * 64 + r] = kv.w;
            float4 vv = *(const float4*)(Vbase + (size_t)r * D_ + c4);
            *(float4*)&Vs[r * 64 + c4] = vv;
        }
        __syncthreads();

        // S = (Q*scale) @ K^T   (4x4 per thread, in registers)
        float s[4][4];
#pragma unroll
        for (int i = 0; i < 4; i++)
#pragma unroll
            for (int j = 0; j < 4; j++) s[i][j] = 0.f;

#pragma unroll 8
        for (int d = 0; d < 64; d++) {
            float4 a4 = *(const float4*)&Qt[d * 64 + ty * 4];
            float4 b4 = *(const float4*)&Kst[d * 64 + tx * 4];
            float ar[4] = {a4.x, a4.y, a4.z, a4.w};
            float br[4] = {b4.x, b4.y, b4.z, b4.w};
#pragma unroll
            for (int i = 0; i < 4; i++)
#pragma unroll
                for (int j = 0; j < 4; j++)
                    s[i][j] = fmaf(ar[i], br[j], s[i][j]);
        }

        // Online softmax per row (reduce across the 16 tx lanes)
#pragma unroll
        for (int i = 0; i < 4; i++) {
            float mx = fmaxf(fmaxf(s[i][0], s[i][1]), fmaxf(s[i][2], s[i][3]));
#pragma unroll
            for (int off = 8; off >= 1; off >>= 1)
                mx = fmaxf(mx, __shfl_xor_sync(0xffffffffu, mx, off));
            float m_new = fmaxf(m_i[i], mx);
            float alpha = __expf(m_i[i] - m_new);
            float rs = 0.f;
#pragma unroll
            for (int j = 0; j < 4; j++) {
                float p = __expf(s[i][j] - m_new);
                s[i][j] = p;
                rs += p;
            }
#pragma unroll
            for (int off = 8; off >= 1; off >>= 1)
                rs += __shfl_xor_sync(0xffffffffu, rs, off);
            l_i[i] = l_i[i] * alpha + rs;
            m_i[i] = m_new;
#pragma unroll
            for (int j = 0; j < 4; j++) acc[i][j] *= alpha;
        }

        // Store P transposed: Ss[k][r]
#pragma unroll
        for (int j = 0; j < 4; j++) {
            float4 pv = make_float4(s[0][j], s[1][j], s[2][j], s[3][j]);
            *(float4*)&Ss[(tx * 4 + j) * SS_STRIDE + ty * 4] = pv;
        }
        __syncthreads();

        // O += P @ V
#pragma unroll 8
        for (int k = 0; k < 64; k++) {
            float4 pa = *(const float4*)&Ss[k * SS_STRIDE + ty * 4];
            float4 vb = *(const float4*)&Vs[k * 64 + tx * 4];
            float ar[4] = {pa.x, pa.y, pa.z, pa.w};
            float br[4] = {vb.x, vb.y, vb.z, vb.w};
#pragma unroll
            for (int i = 0; i < 4; i++)
#pragma unroll
                for (int j = 0; j < 4; j++)
                    acc[i][j] = fmaf(ar[i], br[j], acc[i][j]);
        }
    }

    // Finalize & write out  (layout [B,S,D] so the output projection is a GEMM)
    float* Obase = O + ((size_t)(b * S_ + q0)) * D_ + headoff;
#pragma unroll
    for (int i = 0; i < 4; i++) {
        float inv_l = 1.f / l_i[i];
        float4 o;
        o.x = acc[i][0] * inv_l;
        o.y = acc[i][1] * inv_l;
        o.z = acc[i][2] * inv_l;
        o.w = acc[i][3] * inv_l;
        *(float4*)(Obase + (size_t)(ty * 4 + i) * D_ + tx * 4) = o;
    }
}

// ---------------------------------------------------------------------------
// Launch
// ---------------------------------------------------------------------------
extern "C" void kernel_launch(void* const* d_in, const int* in_sizes, int n_in,
                              void* d_out, int out_size)
{
    const float* x  = (const float*)d_in[0];
    const float* Wq = (const float*)d_in[1];
    const float* bq = (const float*)d_in[2];
    const float* Wk = (const float*)d_in[3];
    const float* bk = (const float*)d_in[4];
    const float* Wv = (const float*)d_in[5];
    const float* bv = (const float*)d_in[6];
    const float* Wo = (const float*)d_in[7];
    const float* bo = (const float*)d_in[8];
    float* out = (float*)d_out;

    float *q, *k, *v, *att;
    cudaGetSymbolAddress((void**)&q,   g_q);
    cudaGetSymbolAddress((void**)&k,   g_k);
    cudaGetSymbolAddress((void**)&v,   g_v);
    cudaGetSymbolAddress((void**)&att, g_att);

    // Q/K/V projections, batched over blockIdx.z
    dim3 ggrid(D_ / BN, M_ / BM, 3);
    proj_gemm<<<ggrid, 256>>>(x, Wq, Wk, Wv, bq, bk, bv, q, k, v, M_, D_, D_);

    // attention
    const int smem_bytes = (64 * 64 * 3 + 64 * SS_STRIDE) * sizeof(float);
    cudaFuncSetAttribute(attn_kernel, cudaFuncAttributeMaxDynamicSharedMemorySize, smem_bytes);
    dim3 agrid(S_ / BQ, H_, B_);
    attn_kernel<<<agrid, 256, smem_bytes>>>(q, k, v, att);

    // output projection -> d_out
    dim3 ogrid(D_ / BN, M_ / BM, 1);
    proj_gemm<<<ogrid, 256>>>(att, Wo, Wo, Wo, bo, bo, bo, out, out, out, M_, D_, D_);
}

// round 2
// speedup vs baseline: 1.6409x; 1.6409x over previous
#include <cuda_runtime.h>
#include <cuda_bf16.h>
#include <math_constants.h>

// Problem constants
#define B_   2
#define S_   2048
#define D_   1024
#define H_   16
#define HD_  64
#define M_   (B_ * S_)      // 4096 rows for the projections

// ---------------------------------------------------------------------------
// Scratch buffers (allocation-free rule: __device__ globals)
// ---------------------------------------------------------------------------
__device__ float g_q[M_ * D_];
__device__ float g_k[M_ * D_];
__device__ float g_v[M_ * D_];
__device__ float g_att[M_ * D_];

// ---------------------------------------------------------------------------
// SGEMM:  C[M,N] = A[M,K] @ W[N,K]^T + bias[N]
// 128x128 block tile, BK=8, 256 threads, 8x8 micro-tile per thread.
// blockIdx.z selects among up to 3 (W, bias, C) triples (used for Q/K/V).
// ---------------------------------------------------------------------------
#define BM 128
#define BN 128
#define BK 8

__global__ __launch_bounds__(256)
void proj_gemm(const float* __restrict__ A,
               const float* __restrict__ W0, const float* __restrict__ W1, const float* __restrict__ W2,
               const float* __restrict__ b0, const float* __restrict__ b1, const float* __restrict__ b2,
               float* __restrict__ C0, float* __restrict__ C1, float* __restrict__ C2,
               int Mdim, int Ndim, int Kdim)
{
    __shared__ float As[BK][BM];
    __shared__ float Bs[BK][BN];

    const int z = blockIdx.z;
    const float* W    = (z == 0) ? W0 : (z == 1) ? W1 : W2;
    const float* bias = (z == 0) ? b0 : (z == 1) ? b1 : b2;
    float*       C    = (z == 0) ? C0 : (z == 1) ? C1 : C2;

    const int tid = threadIdx.x;
    const int tx  = tid & 15;        // 0..15  -> N direction
    const int ty  = tid >> 4;        // 0..15  -> M direction
    const int m0  = blockIdx.y * BM;
    const int n0  = blockIdx.x * BN;

    // loader coordinates: each thread loads one float4 of A and one of W
    const int lr = tid >> 1;         // 0..127 : row within tile
    const int lc = (tid & 1) * 4;    // 0 or 4 : col within 8-wide k-slab

    float acc[8][8];
#pragma unroll
    for (int i = 0; i < 8; i++)
#pragma unroll
        for (int j = 0; j < 8; j++) acc[i][j] = 0.f;

    const float* Arow = A + (size_t)(m0 + lr) * Kdim + lc;
    const float* Wrow = W + (size_t)(n0 + lr) * Kdim + lc;

    for (int k0 = 0; k0 < Kdim; k0 += BK) {
        float4 av = *(const float4*)(Arow + k0);
        float4 bv = *(const float4*)(Wrow + k0);
        __syncthreads();             // previous compute done before smem overwrite
        As[lc + 0][lr] = av.x; As[lc + 1][lr] = av.y;
        As[lc + 2][lr] = av.z; As[lc + 3][lr] = av.w;
        Bs[lc + 0][lr] = bv.x; Bs[lc + 1][lr] = bv.y;
        Bs[lc + 2][lr] = bv.z; Bs[lc + 3][lr] = bv.w;
        __syncthreads();

#pragma unroll
        for (int kk = 0; kk < BK; kk++) {
            float4 a0 = *(const float4*)&As[kk][ty * 8];
            float4 a1 = *(const float4*)&As[kk][ty * 8 + 4];
            float4 bb0 = *(const float4*)&Bs[kk][tx * 8];
            float4 bb1 = *(const float4*)&Bs[kk][tx * 8 + 4];
            float ar[8] = {a0.x, a0.y, a0.z, a0.w, a1.x, a1.y, a1.z, a1.w};
            float br[8] = {bb0.x, bb0.y, bb0.z, bb0.w, bb1.x, bb1.y, bb1.z, bb1.w};
#pragma unroll
            for (int i = 0; i < 8; i++)
#pragma unroll
                for (int j = 0; j < 8; j++)
                    acc[i][j] = fmaf(ar[i], br[j], acc[i][j]);
        }
    }

    // epilogue
#pragma unroll
    for (int i = 0; i < 8; i++) {
        const int row = m0 + ty * 8 + i;
        float* crow = C + (size_t)row * Ndim + n0 + tx * 8;
#pragma unroll
        for (int j4 = 0; j4 < 8; j4 += 4) {
            float4 o;
            o.x = acc[i][j4 + 0] + bias[n0 + tx * 8 + j4 + 0];
            o.y = acc[i][j4 + 1] + bias[n0 + tx * 8 + j4 + 1];
            o.z = acc[i][j4 + 2] + bias[n0 + tx * 8 + j4 + 2];
            o.w = acc[i][j4 + 3] + bias[n0 + tx * 8 + j4 + 3];
            *(float4*)(crow + j4) = o;
        }
    }
}

// ---------------------------------------------------------------------------
// Flash-attention (fp32, online softmax).
// Block: 256 threads (16x16), handles 64 query rows of one (b,h).
// Per thread: 4x4 tile of scores / output.  Row stats via half-warp shuffles.
// ---------------------------------------------------------------------------
#define BQ 64
#define BKV 64
#define SS_STRIDE 68   // padded stride for the P^T tile

__global__ __launch_bounds__(256)
void attn_kernel(const float* __restrict__ Q,
                 const float* __restrict__ K,
                 const float* __restrict__ V,
                 float* __restrict__ O)
{
    extern __shared__ float smem[];
    float* Qt  = smem;                 // [64][64]  Q transposed: Qt[d][r]
    float* Kst = Qt  + 64 * 64;        // [64][64]  K transposed: Kst[d][c]
    float* Vs  = Kst + 64 * 64;        // [64][64]  V natural:    Vs[k][c]
    float* Ss  = Vs  + 64 * 64;        // [64][SS_STRIDE] P transposed: Ss[k][r]

    const int tid = threadIdx.x;
    const int tx  = tid & 15;          // key-col group
    const int ty  = tid >> 4;          // query-row group
    const int b   = blockIdx.z;
    const int h   = blockIdx.y;
    const int q0  = blockIdx.x * BQ;

    const size_t headoff = (size_t)h * HD_;
    const float* Qbase = Q + ((size_t)(b * S_ + q0)) * D_ + headoff;

    // Load Q tile transposed, pre-scaled by 1/sqrt(Hd)
    for (int i = tid; i < 64 * 16; i += 256) {
        int r  = i >> 4;
        int c4 = (i & 15) * 4;
        float4 v = *(const float4*)(Qbase + (size_t)r * D_ + c4);
        Qt[(c4 + 0) * 64 + r] = v.x * 0.125f;
        Qt[(c4 + 1) * 64 + r] = v.y * 0.125f;
        Qt[(c4 + 2) * 64 + r] = v.z * 0.125f;
        Qt[(c4 + 3) * 64 + r] = v.w * 0.125f;
    }

    float acc[4][4];
    float m_i[4], l_i[4];
#pragma unroll
    for (int i = 0; i < 4; i++) {
        m_i[i] = -CUDART_INF_F; l_i[i] = 0.f;
#pragma unroll
        for (int j = 0; j < 4; j++) acc[i][j] = 0.f;
    }

    const int NT = S_ / BKV;
    for (int kt = 0; kt < NT; kt++) {
        const int k0 = kt * BKV;
        const float* Kbase = K + ((size_t)(b * S_ + k0)) * D_ + headoff;
        const float* Vbase = V + ((size_t)(b * S_ + k0)) * D_ + headoff;

        __syncthreads();   // previous PV / Q-load done before overwriting tiles
        for (int i = tid; i < 64 * 16; i += 256) {
            int r  = i >> 4;
            int c4 = (i & 15) * 4;
            float4 kv = *(const float4*)(Kbase + (size_t)r * D_ + c4);
            Kst[(c4 + 0) * 64 + r] = kv.x;
            Kst[(c4 + 1) * 64 + r] = kv.y;
            Kst[(c4 + 2) * 64 + r] = kv.z;
            Kst[(c4 + 3) * 64 + r] = kv.w;
            float4 vv = *(const float4*)(Vbase + (size_t)r * D_ + c4);
            *(float4*)&Vs[r * 64 + c4] = vv;
        }
        __syncthreads();

        // S = (Q*scale) @ K^T   (4x4 per thread, in registers)
        float s[4][4];
#pragma unroll
        for (int i = 0; i < 4; i++)
#pragma unroll
            for (int j = 0; j < 4; j++) s[i][j] = 0.f;

#pragma unroll 8
        for (int d = 0; d < 64; d++) {
            float4 a4 = *(const float4*)&Qt[d * 64 + ty * 4];
            float4 b4 = *(const float4*)&Kst[d * 64 + tx * 4];
            float ar[4] = {a4.x, a4.y, a4.z, a4.w};
            float br[4] = {b4.x, b4.y, b4.z, b4.w};
#pragma unroll
            for (int i = 0; i < 4; i++)
#pragma unroll
                for (int j = 0; j < 4; j++)
                    s[i][j] = fmaf(ar[i], br[j], s[i][j]);
        }

        // Online softmax per row (reduce across the 16 tx lanes)
#pragma unroll
        for (int i = 0; i < 4; i++) {
            float mx = fmaxf(fmaxf(s[i][0], s[i][1]), fmaxf(s[i][2], s[i][3]));
#pragma unroll
            for (int off = 8; off >= 1; off >>= 1)
                mx = fmaxf(mx, __shfl_xor_sync(0xffffffffu, mx, off));
            float m_new = fmaxf(m_i[i], mx);
            float alpha = __expf(m_i[i] - m_new);
            float rs = 0.f;
#pragma unroll
            for (int j = 0; j < 4; j++) {
                float p = __expf(s[i][j] - m_new);
                s[i][j] = p;
                rs += p;
            }
#pragma unroll
            for (int off = 8; off >= 1; off >>= 1)
                rs += __shfl_xor_sync(0xffffffffu, rs, off);
            l_i[i] = l_i[i] * alpha + rs;
            m_i[i] = m_new;
#pragma unroll
            for (int j = 0; j < 4; j++) acc[i][j] *= alpha;
        }

        // Store P transposed: Ss[k][r]
#pragma unroll
        for (int j = 0; j < 4; j++) {
            float4 pv = make_float4(s[0][j], s[1][j], s[2][j], s[3][j]);
            *(float4*)&Ss[(tx * 4 + j) * SS_STRIDE + ty * 4] = pv;
        }
        __syncthreads();

        // O += P @ V
#pragma unroll 8
        for (int k = 0; k < 64; k++) {
            float4 pa = *(const float4*)&Ss[k * SS_STRIDE + ty * 4];
            float4 vb = *(const float4*)&Vs[k * 64 + tx * 4];
            float ar[4] = {pa.x, pa.y, pa.z, pa.w};
            float br[4] = {vb.x, vb.y, vb.z, vb.w};
#pragma unroll
            for (int i = 0; i < 4; i++)
#pragma unroll
                for (int j = 0; j < 4; j++)
                    acc[i][j] = fmaf(ar[i], br[j], acc[i][j]);
        }
    }

    // Finalize & write out  (layout [B,S,D] so the output projection is a GEMM)
    float* Obase = O + ((size_t)(b * S_ + q0)) * D_ + headoff;
#pragma unroll
    for (int i = 0; i < 4; i++) {
        float inv_l = 1.f / l_i[i];
        float4 o;
        o.x = acc[i][0] * inv_l;
        o.y = acc[i][1] * inv_l;
        o.z = acc[i][2] * inv_l;
        o.w = acc[i][3] * inv_l;
        *(float4*)(Obase + (size_t)(ty * 4 + i) * D_ + tx * 4) = o;
    }
}

// ---------------------------------------------------------------------------
// Launch
// ---------------------------------------------------------------------------
extern "C" void kernel_launch(void* const* d_in, const int* in_sizes, int n_in,
                              void* d_out, int out_size)
{
    const float* x  = (const float*)d_in[0];
    const float* Wq = (const float*)d_in[1];
    const float* bq = (const float*)d_in[2];
    const float* Wk = (const float*)d_in[3];
    const float* bk = (const float*)d_in[4];
    const float* Wv = (const float*)d_in[5];
    const float* bv = (const float*)d_in[6];
    const float* Wo = (const float*)d_in[7];
    const float* bo = (const float*)d_in[8];
    float* out = (float*)d_out;

    float *q, *k, *v, *att;
    cudaGetSymbolAddress((void**)&q,   g_q);
    cudaGetSymbolAddress((void**)&k,   g_k);
    cudaGetSymbolAddress((void**)&v,   g_v);
    cudaGetSymbolAddress((void**)&att, g_att);

    // Q/K/V projections, batched over blockIdx.z
    dim3 ggrid(D_ / BN, M_ / BM, 3);
    proj_gemm<<<ggrid, 256>>>(x, Wq, Wk, Wv, bq, bk, bv, q, k, v, M_, D_, D_);

    // attention
    const int smem_bytes = (64 * 64 * 3 + 64 * SS_STRIDE) * sizeof(float);
    cudaFuncSetAttribute(attn_kernel, cudaFuncAttributeMaxDynamicSharedMemorySize, smem_bytes);
    dim3 agrid(S_ / BQ, H_, B_);
    attn_kernel<<<agrid, 256, smem_bytes>>>(q, k, v, att);

    // output projection -> d_out
    dim3 ogrid(D_ / BN, M_ / BM, 1);
    proj_gemm<<<ogrid, 256>>>(att, Wo, Wo, Wo, bo, bo, bo, out, out, out, M_, D_, D_);
}

// round 6
// speedup vs baseline: 5.7365x; 3.4960x over previous
#include <cuda_runtime.h>
#include <cuda_bf16.h>
#include <math_constants.h>
#include <cstdint>

typedef __nv_bfloat16 bf16;

#define B_   2
#define S_   2048
#define D_   1024
#define H_   16
#define HD_  64
#define M_   (B_ * S_)

// fold 1/sqrt(64) * log2(e) into Q so softmax uses exp2
#define QSCALE 0.18033688011112042f

// ---------------------------------------------------------------------------
// helpers
// ---------------------------------------------------------------------------
__device__ __forceinline__ uint32_t smem_to_u32(const void* p) {
    uint32_t a;
    asm("{ .reg .u64 t; cvta.to.shared.u64 t, %1; cvt.u32.u64 %0, t; }" : "=r"(a) : "l"(p));
    return a;
}

#define SWZ(x) ((uint32_t)(x) ^ ((((uint32_t)(x)) >> 3) & 0x70))

#define CPA(dst, src) \
    asm volatile("cp.async.cg.shared.global [%0], [%1], 16;" :: "r"(dst), "l"(src))
#define CPC() asm volatile("cp.async.commit_group;" ::: "memory")
#define CPW(N) asm volatile("cp.async.wait_group %0;" :: "n"(N) : "memory")

#define LDSM4(r0, r1, r2, r3, addr) \
    asm volatile("ldmatrix.sync.aligned.m8n8.x4.shared.b16 {%0,%1,%2,%3}, [%4];" \
        : "=r"(r0), "=r"(r1), "=r"(r2), "=r"(r3) : "r"(addr))
#define LDSM4T(r0, r1, r2, r3, addr) \
    asm volatile("ldmatrix.sync.aligned.m8n8.x4.trans.shared.b16 {%0,%1,%2,%3}, [%4];" \
        : "=r"(r0), "=r"(r1), "=r"(r2), "=r"(r3) : "r"(addr))

#define MMA(d, a, b0, b1) \
    asm volatile("mma.sync.aligned.m16n8k16.row.col.f32.bf16.bf16.f32 " \
        "{%0,%1,%2,%3},{%4,%5,%6,%7},{%8,%9},{%0,%1,%2,%3};" \
        : "+f"((d)[0]), "+f"((d)[1]), "+f"((d)[2]), "+f"((d)[3]) \
        : "r"((a)[0]), "r"((a)[1]), "r"((a)[2]), "r"((a)[3]), "r"(b0), "r"(b1))

__device__ __forceinline__ float ex2(float x) {
    float y;
    asm("ex2.approx.ftz.f32 %0, %1;" : "=f"(y) : "f"(x));
    return y;
}

__device__ __forceinline__ void split2(float a, float b, uint32_t& hi, uint32_t& lo) {
    bf16 ha = __float2bfloat16(a), hb = __float2bfloat16(b);
    bf16 la = __float2bfloat16(a - __bfloat162float(ha));
    bf16 lb = __float2bfloat16(b - __bfloat162float(hb));
    hi = ((uint32_t)__bfloat16_as_ushort(hb) << 16) | (uint32_t)__bfloat16_as_ushort(ha);
    lo = ((uint32_t)__bfloat16_as_ushort(lb) << 16) | (uint32_t)__bfloat16_as_ushort(la);
}

// ---------------------------------------------------------------------------
// Scratch (__device__ globals; allocation-free rule)
// ---------------------------------------------------------------------------
__device__ bf16 g_xh[M_ * D_],  g_xl[M_ * D_];
__device__ bf16 g_wh[4][D_ * D_], g_wl[4][D_ * D_];   // q,k,v,o
__device__ bf16 g_qh[M_ * D_],  g_ql[M_ * D_];
__device__ bf16 g_kh[M_ * D_],  g_kl[M_ * D_];
__device__ bf16 g_vh[M_ * D_],  g_vl[M_ * D_];
__device__ bf16 g_ah[M_ * D_],  g_al[M_ * D_];

// ---------------------------------------------------------------------------
// fp32 -> bf16 hi/lo split
// ---------------------------------------------------------------------------
__global__ __launch_bounds__(256) void cvt_kernel(const float* __restrict__ in,
                                                  bf16* __restrict__ hi, bf16* __restrict__ lo, int n4)
{
    int i = blockIdx.x * blockDim.x + threadIdx.x;
    if (i >= n4) return;
    float4 v = ((const float4*)in)[i];
    uint32_t h0, h1, l0, l1;
    split2(v.x, v.y, h0, l0);
    split2(v.z, v.w, h1, l1);
    ((uint2*)hi)[i] = make_uint2(h0, h1);
    ((uint2*)lo)[i] = make_uint2(l0, l1);
}

// ---------------------------------------------------------------------------
// HMMA projection GEMM: C = A[4096,1024] @ W[1024,1024]^T + bias
// 3-term bf16 split folded as K' = 3072 (48 chunks of 64).
// 128x128 CTA tile, 8 warps (32x64 each), 3-stage cp.async pipeline.
// mode 0: bf16 hi/lo out (scaled); mode 1: fp32 out.
// ---------------------------------------------------------------------------
struct ProjParams {
    const bf16 *Ah, *Al;
    const bf16 *Wh[3], *Wl[3];
    const float *bias[3];
    bf16 *Oh[3], *Ol[3];
    float *Ofp;
    float scale[3];
    int mode[3];
};

#define PJ_SMEM (3 * 32768 + 512)

__global__ __launch_bounds__(256, 2) void proj_tc(ProjParams P)
{
    extern __shared__ char smem[];
    float* bsm = (float*)(smem + 3 * 32768);
    const uint32_t sb = smem_to_u32(smem);
    const int tid = threadIdx.x, lane = tid & 31, wid = tid >> 5;
    const int z = blockIdx.z;
    const int m0 = blockIdx.y * 128, n0 = blockIdx.x * 128;

    const bf16 *Ah = P.Ah, *Al = P.Al;
    const bf16 *Wh = P.Wh[z], *Wl = P.Wl[z];
    if (tid < 128) bsm[tid] = P.bias[z][n0 + tid];

    const int lr = tid >> 3, lc = tid & 7;

    auto ISSUE = [&](int c) {
        if (c < 48) {
            const int seg = c >> 4, kb = (c & 15) * 64;
            const bf16* As = (seg < 2) ? Ah : Al;
            const bf16* Ws = (seg == 1) ? Wl : Wh;
            const uint32_t stg = sb + (c % 3) * 32768;
#pragma unroll
            for (int i = 0; i < 4; i++) {
                int row = lr + i * 32;
                uint32_t off = SWZ(row * 128 + lc * 16);
                CPA(stg + off,         As + (size_t)(m0 + row) * D_ + kb + lc * 8);
                CPA(stg + 16384 + off, Ws + (size_t)(n0 + row) * D_ + kb + lc * 8);
            }
        }
        CPC();
    };
    ISSUE(0); ISSUE(1);

    const int wm = wid >> 1, wn = wid & 1;
    float acc[2][8][4];
#pragma unroll
    for (int a = 0; a < 2; a++)
#pragma unroll
        for (int bnt = 0; bnt < 8; bnt++)
#pragma unroll
            for (int e = 0; e < 4; e++) acc[a][bnt][e] = 0.f;

    for (int c = 0; c < 48; c++) {
        CPW(1);
        __syncthreads();
        ISSUE(c + 2);
        const uint32_t aB = sb + (c % 3) * 32768, wB = aB + 16384;
#pragma unroll
        for (int ks = 0; ks < 4; ks++) {
            uint32_t af[2][4];
#pragma unroll
            for (int mt = 0; mt < 2; mt++) {
                int row = wm * 32 + mt * 16 + (lane & 15);
                int kb2 = ks * 16 + (lane >> 4) * 8;
                LDSM4(af[mt][0], af[mt][1], af[mt][2], af[mt][3], aB + SWZ(row * 128 + kb2 * 2));
            }
#pragma unroll
            for (int gg = 0; gg < 4; gg++) {
                int part = lane >> 3;
                int nrow = wn * 64 + gg * 16 + ((part >> 1) << 3) + (lane & 7);
                int kb2 = ks * 16 + ((part & 1) << 3);
                uint32_t b0, b1, b2, b3;
                LDSM4(b0, b1, b2, b3, wB + SWZ(nrow * 128 + kb2 * 2));
                MMA(acc[0][2 * gg], af[0], b0, b1); MMA(acc[0][2 * gg + 1], af[0], b2, b3);
                MMA(acc[1][2 * gg], af[1], b0, b1); MMA(acc[1][2 * gg + 1], af[1], b2, b3);
            }
        }
    }

    // epilogue
    const int g = lane >> 2, t4 = lane & 3;
    const int mode = P.mode[z];
    const float scv = P.scale[z];
#pragma unroll
    for (int mt = 0; mt < 2; mt++) {
        int r0 = m0 + wm * 32 + mt * 16 + g;
#pragma unroll
        for (int nt = 0; nt < 8; nt++) {
            int cloc = wn * 64 + nt * 8 + t4 * 2;
            float b0v = bsm[cloc], b1v = bsm[cloc + 1];
            float v0 = (acc[mt][nt][0] + b0v) * scv, v1 = (acc[mt][nt][1] + b1v) * scv;
            float v2 = (acc[mt][nt][2] + b0v) * scv, v3 = (acc[mt][nt][3] + b1v) * scv;
            size_t o0 = (size_t)r0 * D_ + n0 + cloc;
            size_t o1 = o0 + 8 * (size_t)D_;
            if (mode == 1) {
                *(float2*)(P.Ofp + o0) = make_float2(v0, v1);
                *(float2*)(P.Ofp + o1) = make_float2(v2, v3);
            } else {
                uint32_t hh, ll;
                split2(v0, v1, hh, ll);
                *(uint32_t*)(P.Oh[z] + o0) = hh; *(uint32_t*)(P.Ol[z] + o0) = ll;
                split2(v2, v3, hh, ll);
                *(uint32_t*)(P.Oh[z] + o1) = hh; *(uint32_t*)(P.Ol[z] + o1) = ll;
            }
        }
    }
}

// ---------------------------------------------------------------------------
// Flash attention on HMMA.  CTA = 128 queries of one (b,h), 8 warps x 16 rows.
// KV tiles of 128, hi/lo, double-buffered cp.async.  V in natural [s,hd]
// layout consumed via ldmatrix.trans.
// ---------------------------------------------------------------------------
#define AT_SMEM (32768 + 2 * 65536)

__global__ __launch_bounds__(256, 1) void attn_tc(
    const bf16* __restrict__ Qh, const bf16* __restrict__ Ql,
    const bf16* __restrict__ Kh, const bf16* __restrict__ Kl,
    const bf16* __restrict__ Vh, const bf16* __restrict__ Vl,
    bf16* __restrict__ Oh, bf16* __restrict__ Ol)
{
    extern __shared__ char smem[];
    const uint32_t sb = smem_to_u32(smem);
    const int tid = threadIdx.x, lane = tid & 31, wid = tid >> 5;
    const int b = blockIdx.z, h = blockIdx.y, q0 = blockIdx.x * 128;
    const int lr = tid >> 3, lc = tid & 7;
    const int wrow = wid * 16;

    // Q tile loads (committed together with tile 0)
#pragma unroll
    for (int i = 0; i < 4; i++) {
        int row = lr + i * 32;
        uint32_t off = SWZ(row * 128 + lc * 16);
        size_t gq = (size_t)(b * S_ + q0 + row) * D_ + h * 64 + lc * 8;
        CPA(sb + off,         Qh + gq);
        CPA(sb + 16384 + off, Ql + gq);
    }

    auto ISSUE = [&](int t) {
        if (t < 16) {
            const int k0 = t * 128;
            const uint32_t st = sb + 32768 + (t & 1) * 65536;
#pragma unroll
            for (int i = 0; i < 4; i++) {
                int row = lr + i * 32;
                uint32_t off = SWZ(row * 128 + lc * 16);
                size_t gk = (size_t)(b * S_ + k0 + row) * D_ + h * 64 + lc * 8;
                CPA(st + off,         Kh + gk);
                CPA(st + 16384 + off, Kl + gk);
                CPA(st + 32768 + off, Vh + gk);
                CPA(st + 49152 + off, Vl + gk);
            }
        }
        CPC();
    };
    ISSUE(0); ISSUE(1);

    float o[8][4];
#pragma unroll
    for (int nt = 0; nt < 8; nt++)
#pragma unroll
        for (int e = 0; e < 4; e++) o[nt][e] = 0.f;
    float mr0 = -CUDART_INF_F, mr1 = -CUDART_INF_F, l0 = 0.f, l1 = 0.f;
    const int g = lane >> 2, t4 = lane & 3;

    for (int t = 0; t < 16; t++) {
        CPW(1);
        __syncthreads();
        const uint32_t kH = sb + 32768 + (t & 1) * 65536;
        const uint32_t kL = kH + 16384, vH = kH + 32768, vL = kH + 49152;

        // ---- S = Qh*Kh + Ql*Kh + Qh*Kl
        float sc[16][4];
#pragma unroll
        for (int nt = 0; nt < 16; nt++)
#pragma unroll
            for (int e = 0; e < 4; e++) sc[nt][e] = 0.f;

#pragma unroll
        for (int ks = 0; ks < 4; ks++) {
            uint32_t aH[4], aL[4];
            {
                int row = wrow + (lane & 15);
                int kb2 = ks * 16 + (lane >> 4) * 8;
                uint32_t off = SWZ(row * 128 + kb2 * 2);
                LDSM4(aH[0], aH[1], aH[2], aH[3], sb + off);
                LDSM4(aL[0], aL[1], aL[2], aL[3], sb + 16384 + off);
            }
#pragma unroll
            for (int gg = 0; gg < 8; gg++) {
                int part = lane >> 3;
                int nrow = gg * 16 + ((part >> 1) << 3) + (lane & 7);
                int kb2 = ks * 16 + ((part & 1) << 3);
                uint32_t off = SWZ(nrow * 128 + kb2 * 2);
                uint32_t b0, b1, b2, b3;
                LDSM4(b0, b1, b2, b3, kH + off);
                MMA(sc[2 * gg], aH, b0, b1); MMA(sc[2 * gg + 1], aH, b2, b3);
                MMA(sc[2 * gg], aL, b0, b1); MMA(sc[2 * gg + 1], aL, b2, b3);
                LDSM4(b0, b1, b2, b3, kL + off);
                MMA(sc[2 * gg], aH, b0, b1); MMA(sc[2 * gg + 1], aH, b2, b3);
            }
        }

        // ---- online softmax (rows g and g+8; quad reduction over t4 lanes)
        float mx0 = -CUDART_INF_F, mx1 = -CUDART_INF_F;
#pragma unroll
        for (int nt = 0; nt < 16; nt++) {
            mx0 = fmaxf(mx0, fmaxf(sc[nt][0], sc[nt][1]));
            mx1 = fmaxf(mx1, fmaxf(sc[nt][2], sc[nt][3]));
        }
        mx0 = fmaxf(mx0, __shfl_xor_sync(0xffffffffu, mx0, 1));
        mx0 = fmaxf(mx0, __shfl_xor_sync(0xffffffffu, mx0, 2));
        mx1 = fmaxf(mx1, __shfl_xor_sync(0xffffffffu, mx1, 1));
        mx1 = fmaxf(mx1, __shfl_xor_sync(0xffffffffu, mx1, 2));
        const float mn0 = fmaxf(mr0, mx0), mn1 = fmaxf(mr1, mx1);
        const float al0 = ex2(mr0 - mn0), al1 = ex2(mr1 - mn1);
        float s0 = 0.f, s1 = 0.f;
#pragma unroll
        for (int nt = 0; nt < 16; nt++) {
            sc[nt][0] = ex2(sc[nt][0] - mn0); s0 += sc[nt][0];
            sc[nt][1] = ex2(sc[nt][1] - mn0); s0 += sc[nt][1];
            sc[nt][2] = ex2(sc[nt][2] - mn1); s1 += sc[nt][2];
            sc[nt][3] = ex2(sc[nt][3] - mn1); s1 += sc[nt][3];
        }
        s0 += __shfl_xor_sync(0xffffffffu, s0, 1);
        s0 += __shfl_xor_sync(0xffffffffu, s0, 2);
        s1 += __shfl_xor_sync(0xffffffffu, s1, 1);
        s1 += __shfl_xor_sync(0xffffffffu, s1, 2);
        l0 = l0 * al0 + s0; l1 = l1 * al1 + s1;
        mr0 = mn0; mr1 = mn1;
#pragma unroll
        for (int nt = 0; nt < 8; nt++) {
            o[nt][0] *= al0; o[nt][1] *= al0;
            o[nt][2] *= al1; o[nt][3] *= al1;
        }

        // ---- O += Ph*Vh + Pl*Vh + Ph*Vl
#pragma unroll
        for (int j = 0; j < 8; j++) {
            uint32_t ph[4], pl[4];
            split2(sc[2 * j][0],     sc[2 * j][1],     ph[0], pl[0]);
            split2(sc[2 * j][2],     sc[2 * j][3],     ph[1], pl[1]);
            split2(sc[2 * j + 1][0], sc[2 * j + 1][1], ph[2], pl[2]);
            split2(sc[2 * j + 1][2], sc[2 * j + 1][3], ph[3], pl[3]);
            int part = lane >> 3;
            int krow = j * 16 + ((part & 1) << 3) + (lane & 7);
#pragma unroll
            for (int g16 = 0; g16 < 4; g16++) {
                int nb = g16 * 16 + ((part >> 1) << 3);
                uint32_t off = SWZ(krow * 128 + nb * 2);
                uint32_t v0, v1, v2, v3;
                LDSM4T(v0, v1, v2, v3, vH + off);
                MMA(o[2 * g16], ph, v0, v1); MMA(o[2 * g16 + 1], ph, v2, v3);
                MMA(o[2 * g16], pl, v0, v1); MMA(o[2 * g16 + 1], pl, v2, v3);
                LDSM4T(v0, v1, v2, v3, vL + off);
                MMA(o[2 * g16], ph, v0, v1); MMA(o[2 * g16 + 1], ph, v2, v3);
            }
        }
        __syncthreads();
        ISSUE(t + 2);
    }

    // ---- finalize and write bf16 hi/lo at [B,S,D]
    const float i0 = 1.f / l0, i1 = 1.f / l1;
    const int r0 = q0 + wrow + g, r1 = r0 + 8;
#pragma unroll
    for (int nt = 0; nt < 8; nt++) {
        int col = h * 64 + nt * 8 + t4 * 2;
        uint32_t hh, ll;
        split2(o[nt][0] * i0, o[nt][1] * i0, hh, ll);
        size_t o0 = (size_t)(b * S_ + r0) * D_ + col;
        *(uint32_t*)(Oh + o0) = hh; *(uint32_t*)(Ol + o0) = ll;
        split2(o[nt][2] * i1, o[nt][3] * i1, hh, ll);
        size_t o1 = (size_t)(b * S_ + r1) * D_ + col;
        *(uint32_t*)(Oh + o1) = hh; *(uint32_t*)(Ol + o1) = ll;
    }
}

// ---------------------------------------------------------------------------
// Launch
// ---------------------------------------------------------------------------
extern "C" void kernel_launch(void* const* d_in, const int* in_sizes, int n_in,
                              void* d_out, int out_size)
{
    const float* x  = (const float*)d_in[0];
    const float* Wq = (const float*)d_in[1];
    const float* bq = (const float*)d_in[2];
    const float* Wk = (const float*)d_in[3];
    const float* bk = (const float*)d_in[4];
    const float* Wv = (const float*)d_in[5];
    const float* bv = (const float*)d_in[6];
    const float* Wo = (const float*)d_in[7];
    const float* bo = (const float*)d_in[8];
    float* out = (float*)d_out;

    bf16 *xh, *xl, *wh, *wl, *qh, *ql, *kh, *kl, *vh, *vl, *ah, *al;
    cudaGetSymbolAddress((void**)&xh, g_xh); cudaGetSymbolAddress((void**)&xl, g_xl);
    cudaGetSymbolAddress((void**)&wh, g_wh); cudaGetSymbolAddress((void**)&wl, g_wl);
    cudaGetSymbolAddress((void**)&qh, g_qh); cudaGetSymbolAddress((void**)&ql, g_ql);
    cudaGetSymbolAddress((void**)&kh, g_kh); cudaGetSymbolAddress((void**)&kl, g_kl);
    cudaGetSymbolAddress((void**)&vh, g_vh); cudaGetSymbolAddress((void**)&vl, g_vl);
    cudaGetSymbolAddress((void**)&ah, g_ah); cudaGetSymbolAddress((void**)&al, g_al);

    const int WN = D_ * D_;
    cvt_kernel<<<(M_ * D_ / 4 + 255) / 256, 256>>>(x, xh, xl, M_ * D_ / 4);
    cvt_kernel<<<(WN / 4 + 255) / 256, 256>>>(Wq, wh + 0 * WN, wl + 0 * WN, WN / 4);
    cvt_kernel<<<(WN / 4 + 255) / 256, 256>>>(Wk, wh + 1 * WN, wl + 1 * WN, WN / 4);
    cvt_kernel<<<(WN / 4 + 255) / 256, 256>>>(Wv, wh + 2 * WN, wl + 2 * WN, WN / 4);
    cvt_kernel<<<(WN / 4 + 255) / 256, 256>>>(Wo, wh + 3 * WN, wl + 3 * WN, WN / 4);

    cudaFuncSetAttribute(proj_tc, cudaFuncAttributeMaxDynamicSharedMemorySize, PJ_SMEM);
    cudaFuncSetAttribute(attn_tc, cudaFuncAttributeMaxDynamicSharedMemorySize, AT_SMEM);

    // QKV projection (z batches the 3 weight sets)
    {
        ProjParams P;
        P.Ah = xh; P.Al = xl;
        P.Wh[0] = wh;          P.Wl[0] = wl;
        P.Wh[1] = wh + WN;     P.Wl[1] = wl + WN;
        P.Wh[2] = wh + 2 * WN; P.Wl[2] = wl + 2 * WN;
        P.bias[0] = bq; P.bias[1] = bk; P.bias[2] = bv;
        P.Oh[0] = qh; P.Ol[0] = ql;
        P.Oh[1] = kh; P.Ol[1] = kl;
        P.Oh[2] = vh; P.Ol[2] = vl;
        P.Ofp = nullptr;
        P.scale[0] = QSCALE; P.scale[1] = 1.f; P.scale[2] = 1.f;
        P.mode[0] = 0; P.mode[1] = 0; P.mode[2] = 0;
        dim3 grid(D_ / 128, M_ / 128, 3);
        proj_tc<<<grid, 256, PJ_SMEM>>>(P);
    }

    // attention
    {
        dim3 grid(S_ / 128, H_, B_);
        attn_tc<<<grid, 256, AT_SMEM>>>(qh, ql, kh, kl, vh, vl, ah, al);
    }

    // output projection (fp32 out)
    {
        ProjParams P;
        P.Ah = ah; P.Al = al;
        P.Wh[0] = wh + 3 * WN; P.Wl[0] = wl + 3 * WN;
        P.Wh[1] = P.Wh[0]; P.Wl[1] = P.Wl[0];
        P.Wh[2] = P.Wh[0]; P.Wl[2] = P.Wl[0];
        P.bias[0] = bo; P.bias[1] = bo; P.bias[2] = bo;
        P.Oh[0] = P.Oh[1] = P.Oh[2] = nullptr;
        P.Ol[0] = P.Ol[1] = P.Ol[2] = nullptr;
        P.Ofp = out;
        P.scale[0] = P.scale[1] = P.scale[2] = 1.f;
        P.mode[0] = P.mode[1] = P.mode[2] = 1;
        dim3 grid(D_ / 128, M_ / 128, 1);
        proj_tc<<<grid, 256, PJ_SMEM>>>(P);
    }
}